// round 9
// baseline (speedup 1.0000x reference)
#include <cuda_runtime.h>
#include <cstdint>

#define BATCH 4096
#define T_STEPS 50
#define HID 256
#define HSTR (T_STEPS * HID)   // out row stride: 12800 floats
#define KAZ 384                // packed A width: 256 (h) + 128 (z)

// ---------------- scratch (no allocations allowed) ----------------
__device__ float g_xhi[BATCH * 256],  g_xlo[BATCH * 256];     // zs split
__device__ float g_w1h[512 * 256],    g_w1l[512 * 256];
__device__ float g_w2h[256 * 512],    g_w2l[256 * 512];
__device__ float g_w3h[128 * 256],    g_w3l[128 * 256];
__device__ float g_h1h[BATCH * 512],  g_h1l[BATCH * 512];
__device__ float g_h2h[BATCH * 256],  g_h2l[BATCH * 256];
__device__ float g_az [BATCH * KAZ];   // [4096][384]: cols 0..255 h (tf32), 256..383 z (tf32)
__device__ float g_wc [1024 * KAZ];    // permuted [Whh | Wih] tf32; row r'=q*256+g*64+jj
__device__ float g_bias[1024];         // permuted b_ih + b_hh
__device__ float g_c [256 * BATCH];    // fp32 TRANSPOSED [256][4096]

// ---------------- helpers ----------------
__device__ __forceinline__ uint32_t f2tf(float x) {
    uint32_t r;
    asm("cvt.rna.tf32.f32 %0, %1;" : "=r"(r) : "f"(x));
    return r;
}
__device__ __forceinline__ float f2tf_f(float x) { return __uint_as_float(f2tf(x)); }
__device__ __forceinline__ uint32_t smem_u32(const void* p) {
    uint32_t a;
    asm("{ .reg .u64 t; cvta.to.shared.u64 t, %1; cvt.u32.u64 %0, t; }" : "=r"(a) : "l"(p));
    return a;
}
__device__ __forceinline__ void cp16(uint32_t d, const void* s) {
    asm volatile("cp.async.cg.shared.global [%0], [%1], 16;" :: "r"(d), "l"(s));
}
__device__ __forceinline__ void cp_commit() { asm volatile("cp.async.commit_group;"); }
__device__ __forceinline__ void cp_wait1()  { asm volatile("cp.async.wait_group 1;" ::: "memory"); }
__device__ __forceinline__ void cp_wait0()  { asm volatile("cp.async.wait_group 0;" ::: "memory"); }
__device__ __forceinline__ void mma8(float* c, const uint32_t* a, const uint32_t* b) {
    asm volatile(
        "mma.sync.aligned.m16n8k8.row.col.f32.tf32.tf32.f32 "
        "{%0,%1,%2,%3}, {%4,%5,%6,%7}, {%8,%9}, {%0,%1,%2,%3};"
        : "+f"(c[0]), "+f"(c[1]), "+f"(c[2]), "+f"(c[3])
        : "r"(a[0]), "r"(a[1]), "r"(a[2]), "r"(a[3]), "r"(b[0]), "r"(b[1]));
}
__device__ __forceinline__ float sigmoidf_fast(float x) {
    return __fdividef(1.0f, 1.0f + __expf(-x));
}
__device__ __forceinline__ float tanhf_fast(float x) {
    return fmaf(2.0f, __fdividef(1.0f, 1.0f + __expf(-2.0f * x)), -1.0f);
}

// ---------------- setup kernels ----------------
__global__ void conv_split(const float* __restrict__ zs, const float* __restrict__ W1,
                           const float* __restrict__ W2, const float* __restrict__ W3) {
    int i = blockIdx.x * 256 + threadIdx.x;
    const float* s; float *hi, *lo; int off;
    if      (i < 1048576) { s = zs; hi = g_xhi; lo = g_xlo; off = i; }
    else if (i < 1179648) { s = W1; hi = g_w1h; lo = g_w1l; off = i - 1048576; }
    else if (i < 1310720) { s = W2; hi = g_w2h; lo = g_w2l; off = i - 1179648; }
    else if (i < 1343488) { s = W3; hi = g_w3h; lo = g_w3l; off = i - 1310720; }
    else return;
    float x = s[off];
    float h = f2tf_f(x);
    hi[off] = h;
    lo[off] = f2tf_f(x - h);
}
// g_wc row r' = q*256 + g*64 + jj  <-  gate row gr = g*256 + q*64 + jj
__global__ void conv_wc(const float* __restrict__ whh, const float* __restrict__ wih,
                        const float* __restrict__ bih, const float* __restrict__ bhh) {
    int k = threadIdx.x;          // 0..383
    int r = blockIdx.x;           // 0..1023
    int q = r >> 8, g = (r >> 6) & 3, jj = r & 63;
    int gr = g * 256 + q * 64 + jj;
    float v = (k < 256) ? whh[(size_t)gr * 256 + k] : wih[(size_t)gr * 128 + (k - 256)];
    g_wc[(size_t)r * KAZ + k] = f2tf_f(v);
    if (k == 0) g_bias[r] = bih[gr] + bhh[gr];
}
// zero h-part of g_az and all of g_c
__global__ void init_state() {
    int i = blockIdx.x * 256 + threadIdx.x;   // 0 .. 4096*256-1
    int row = i >> 8, col = i & 255;
    g_az[(size_t)row * KAZ + col] = 0.0f;
    g_c[(size_t)col * BATCH + row] = 0.0f;
}

// ================= split-tf32 GEMM (MLP), 256 threads, 128x128 tile =========
#define SG_STRIDE 36
#define SG_HALF   (128 * SG_STRIDE * 4)   // 18432
#define SG_STAGE  (4 * SG_HALF)           // 73728: Ahi|Alo|Bhi|Blo
#define SG_SMEM   (3 * SG_STAGE)          // 221184
#define SG_GS     133

__device__ __forceinline__ void sg_issue(char* sm, int st,
    const float* Ahi, const float* Alo, const float* Bhi, const float* Blo,
    int aBase, int bBase, int K, int tid)
{
    uint32_t base = smem_u32(sm + (st % 3) * SG_STAGE);
    const int k0 = st * 32;
    const int srow = tid >> 3, sk4 = (tid & 7) << 2;
    #pragma unroll
    for (int i = 0; i < 4; i++) {
        int row = i * 32 + srow;
        uint32_t d = base + (uint32_t)(row * SG_STRIDE + sk4) * 4;
        size_t ao = (size_t)(aBase + row) * K + k0 + sk4;
        size_t bo = (size_t)(bBase + row) * K + k0 + sk4;
        cp16(d,               Ahi + ao);
        cp16(d + SG_HALF,     Alo + ao);
        cp16(d + 2 * SG_HALF, Bhi + bo);
        cp16(d + 3 * SG_HALF, Blo + bo);
    }
    cp_commit();
}

// outMode: 0 = split hi/lo (Chi/Clo, ldC=N), 1 = tf32 single into Chi with ldC
__global__ void __launch_bounds__(256, 1) mma_gemm_split(
    const float* __restrict__ Ahi, const float* __restrict__ Alo,
    const float* __restrict__ Bhi, const float* __restrict__ Blo,
    const float* __restrict__ bias,
    float* __restrict__ Chi, float* __restrict__ Clo,
    int M, int N, int K, int relu, int ldC)
{
    extern __shared__ char sm[];
    const int tid = threadIdx.x;
    const int wid = tid >> 5, lane = tid & 31;
    const int wm = wid & 3, wn = wid >> 2;
    const int bm = blockIdx.y * 128, bn = blockIdx.x * 128;
    const int NC = K >> 5;

    float acc[2][8][4];
    #pragma unroll
    for (int mi = 0; mi < 2; mi++)
        #pragma unroll
        for (int ni = 0; ni < 8; ni++)
            #pragma unroll
            for (int v = 0; v < 4; v++) acc[mi][ni][v] = 0.0f;

    sg_issue(sm, 0, Ahi, Alo, Bhi, Blo, bm, bn, K, tid);
    sg_issue(sm, 1, Ahi, Alo, Bhi, Blo, bm, bn, K, tid);

    const int ar = wm * 32 + (lane >> 2);
    const int bc = wn * 64 + (lane >> 2);
    const int q  = lane & 3;

    #pragma unroll 1
    for (int ch = 0; ch < NC; ch++) {
        if (ch == NC - 1) cp_wait0(); else cp_wait1();
        __syncthreads();
        if (ch + 2 < NC) sg_issue(sm, ch + 2, Ahi, Alo, Bhi, Blo, bm, bn, K, tid);
        const uint32_t* Ah = (const uint32_t*)(sm + (ch % 3) * SG_STAGE);
        const uint32_t* Al = Ah + SG_HALF / 4;
        const uint32_t* Bh = Ah + 2 * SG_HALF / 4;
        const uint32_t* Bl = Ah + 3 * SG_HALF / 4;
        #pragma unroll
        for (int kk = 0; kk < 4; kk++) {
            const int kb = kk * 8 + q;
            uint32_t ah[2][4], al[2][4], bh[8][2], bl[8][2];
            #pragma unroll
            for (int mi = 0; mi < 2; mi++) {
                const int r0 = (ar + mi * 16) * SG_STRIDE;
                const int r8 = (ar + mi * 16 + 8) * SG_STRIDE;
                ah[mi][0] = Ah[r0 + kb]; ah[mi][1] = Ah[r8 + kb];
                ah[mi][2] = Ah[r0 + kb + 4]; ah[mi][3] = Ah[r8 + kb + 4];
                al[mi][0] = Al[r0 + kb]; al[mi][1] = Al[r8 + kb];
                al[mi][2] = Al[r0 + kb + 4]; al[mi][3] = Al[r8 + kb + 4];
            }
            #pragma unroll
            for (int ni = 0; ni < 8; ni++) {
                const int rB = (bc + ni * 8) * SG_STRIDE;
                bh[ni][0] = Bh[rB + kb]; bh[ni][1] = Bh[rB + kb + 4];
                bl[ni][0] = Bl[rB + kb]; bl[ni][1] = Bl[rB + kb + 4];
            }
            #pragma unroll
            for (int mi = 0; mi < 2; mi++)
                #pragma unroll
                for (int ni = 0; ni < 8; ni++) {
                    mma8(acc[mi][ni], ah[mi], bl[ni]);
                    mma8(acc[mi][ni], al[mi], bh[ni]);
                    mma8(acc[mi][ni], ah[mi], bh[ni]);
                }
        }
    }
    __syncthreads();

    {
        float* gs = (float*)sm;
        const int grow = wm * 32 + (lane >> 2);
        const int gcol = wn * 64 + ((lane & 3) << 1);
        #pragma unroll
        for (int mi = 0; mi < 2; mi++)
            #pragma unroll
            for (int ni = 0; ni < 8; ni++) {
                int r = grow + mi * 16, cc = gcol + ni * 8;
                gs[r * SG_GS + cc]           = acc[mi][ni][0];
                gs[r * SG_GS + cc + 1]       = acc[mi][ni][1];
                gs[(r + 8) * SG_GS + cc]     = acc[mi][ni][2];
                gs[(r + 8) * SG_GS + cc + 1] = acc[mi][ni][3];
            }
    }
    __syncthreads();

    const float* gs = (const float*)sm;
    #pragma unroll
    for (int i = 0; i < 16; i++) {
        int row = i * 8 + wid;
        #pragma unroll
        for (int cc = 0; cc < 4; cc++) {
            int col = cc * 32 + lane;
            if (bn + col >= N) continue;
            float v = gs[row * SG_GS + col] + bias[bn + col];
            if (relu) v = fmaxf(v, 0.0f);
            size_t o = (size_t)(bm + row) * ldC + bn + col;
            if (Clo) {
                float h = f2tf_f(v);
                Chi[o] = h;
                Clo[o] = f2tf_f(v - h);
            } else {
                Chi[o] = f2tf_f(v);
            }
        }
    }
}

// ================= fused LSTM step, 512 threads, 128 x 256-col tile =========
// gates[128, 256cols=(g,jj)] = g_az[bm:bm+128, 0:384] @ g_wc[bBase:bBase+256]^T
// (h | z fused, K=384). Uniform over t: h-part is zero at t=0.
#define ST_STRIDE 36
#define ST_A     (128 * ST_STRIDE * 4)    // 18432
#define ST_B     (256 * ST_STRIDE * 4)    // 36864
#define ST_STAGE (ST_A + ST_B)            // 55296
#define ST_GS    261
#define ST_HS    (128 * ST_GS * 4)        // 133632
#define ST_BIAS  (ST_HS + 128 * 65 * 4)   // 166912
#define ST_SMEM  (ST_BIAS + 256 * 4)      // 167936

__device__ __forceinline__ void st_issue(char* sm, int st, int bm, int bBase, int tid)
{
    uint32_t base = smem_u32(sm + (st % 3) * ST_STAGE);
    const int k0 = st * 32;
    const int srow = tid >> 3, sk4 = (tid & 7) << 2;   // srow 0..63
    #pragma unroll
    for (int i = 0; i < 2; i++) {
        int row = i * 64 + srow;
        cp16(base + (uint32_t)(row * ST_STRIDE + sk4) * 4,
             g_az + (size_t)(bm + row) * KAZ + k0 + sk4);
    }
    #pragma unroll
    for (int i = 0; i < 4; i++) {
        int row = i * 64 + srow;
        cp16(base + ST_A + (uint32_t)(row * ST_STRIDE + sk4) * 4,
             g_wc + (size_t)(bBase + row) * KAZ + k0 + sk4);
    }
    cp_commit();
}

__global__ void __launch_bounds__(512, 1)
lstm_step(float* __restrict__ out, int t)
{
    extern __shared__ char sm[];
    const int tid  = threadIdx.x;
    const int wid  = tid >> 5;
    const int lane = tid & 31;
    const int wm   = wid & 3, wn = wid >> 2;   // 4 x 4 warp grid
    const int bm   = blockIdx.y * 128;
    const int jb   = blockIdx.x * 64;
    const int bBase = blockIdx.x * 256;
    const int NC = KAZ / 32;                   // 12

    float* sbias = (float*)(sm + ST_BIAS);
    if (tid < 256) sbias[tid] = g_bias[bBase + tid];

    float acc[2][8][4];
    #pragma unroll
    for (int mi = 0; mi < 2; mi++)
        #pragma unroll
        for (int ni = 0; ni < 8; ni++)
            #pragma unroll
            for (int v = 0; v < 4; v++) acc[mi][ni][v] = 0.0f;

    st_issue(sm, 0, bm, bBase, tid);
    st_issue(sm, 1, bm, bBase, tid);

    const int ar = wm * 32 + (lane >> 2);
    const int bc = wn * 64 + (lane >> 2);
    const int q  = lane & 3;

    #pragma unroll 1
    for (int ch = 0; ch < NC; ch++) {
        if (ch == NC - 1) cp_wait0(); else cp_wait1();
        __syncthreads();
        if (ch + 2 < NC) st_issue(sm, ch + 2, bm, bBase, tid);
        const uint32_t* As = (const uint32_t*)(sm + (ch % 3) * ST_STAGE);
        const uint32_t* Bs = As + ST_A / 4;
        #pragma unroll
        for (int kk = 0; kk < 4; kk++) {
            const int kb = kk * 8 + q;
            uint32_t a[2][4], b[8][2];
            #pragma unroll
            for (int mi = 0; mi < 2; mi++) {
                const int r0 = (ar + mi * 16) * ST_STRIDE;
                const int r8 = (ar + mi * 16 + 8) * ST_STRIDE;
                a[mi][0] = As[r0 + kb];
                a[mi][1] = As[r8 + kb];
                a[mi][2] = As[r0 + kb + 4];
                a[mi][3] = As[r8 + kb + 4];
            }
            #pragma unroll
            for (int ni = 0; ni < 8; ni++) {
                const int rB = (bc + ni * 8) * ST_STRIDE;
                b[ni][0] = Bs[rB + kb];
                b[ni][1] = Bs[rB + kb + 4];
            }
            #pragma unroll
            for (int mi = 0; mi < 2; mi++)
                #pragma unroll
                for (int ni = 0; ni < 8; ni++)
                    mma8(acc[mi][ni], a[mi], b[ni]);
        }
    }
    __syncthreads();

    // stage gates: gs[128][261], col = g*64 + jj
    {
        float* gs = (float*)sm;
        const int grow = wm * 32 + (lane >> 2);
        const int gcol = wn * 64 + ((lane & 3) << 1);
        #pragma unroll
        for (int mi = 0; mi < 2; mi++)
            #pragma unroll
            for (int ni = 0; ni < 8; ni++) {
                int r = grow + mi * 16, cc = gcol + ni * 8;
                gs[r * ST_GS + cc]           = acc[mi][ni][0];
                gs[r * ST_GS + cc + 1]       = acc[mi][ni][1];
                gs[(r + 8) * ST_GS + cc]     = acc[mi][ni][2];
                gs[(r + 8) * ST_GS + cc + 1] = acc[mi][ni][3];
            }
    }
    __syncthreads();

    // ---------------- LSTM cell epilogue ----------------
    const float* gs = (const float*)sm;
    float* hsm = (float*)(sm + ST_HS);
    const int rloc = tid & 127;
    const int quarter = tid >> 7;
    const int brow = bm + rloc;

    #pragma unroll
    for (int i = 0; i < 16; i++) {
        const int jj = i * 4 + quarter;
        float gi = gs[rloc * ST_GS + jj]       + sbias[jj];
        float gf = gs[rloc * ST_GS + 64 + jj]  + sbias[64 + jj];
        float gg = gs[rloc * ST_GS + 128 + jj] + sbias[128 + jj];
        float go = gs[rloc * ST_GS + 192 + jj] + sbias[192 + jj];
        float cp = g_c[(size_t)(jb + jj) * BATCH + brow];
        float vi = sigmoidf_fast(gi);
        float vf = sigmoidf_fast(gf);
        float vg = tanhf_fast(gg);
        float vo = sigmoidf_fast(go);
        float cn = vf * cp + vi * vg;
        g_c[(size_t)(jb + jj) * BATCH + brow] = cn;
        hsm[rloc * 65 + jj] = vo * tanhf_fast(cn);
    }
    __syncthreads();

    // coalesced h writes: out (fp32, strided) + g_az h-part (tf32)
    #pragma unroll
    for (int i = 0; i < 16; i++) {
        int row = i * 8 + (wid >> 1);
        int col = (wid & 1) * 32 + lane;
        float v = hsm[row * 65 + col];
        out[(size_t)(bm + row) * HSTR + (size_t)t * HID + jb + col] = v;
        g_az[(size_t)(bm + row) * KAZ + jb + col] = f2tf_f(v);
    }
}

// ---------------- launch ----------------
extern "C" void kernel_launch(void* const* d_in, const int* in_sizes, int n_in,
                              void* d_out, int out_size)
{
    const float* zs  = (const float*)d_in[0];
    const float* W1  = (const float*)d_in[1];
    const float* b1  = (const float*)d_in[2];
    const float* W2  = (const float*)d_in[3];
    const float* b2  = (const float*)d_in[4];
    const float* W3  = (const float*)d_in[5];
    const float* b3  = (const float*)d_in[6];
    const float* Wih = (const float*)d_in[7];
    const float* Whh = (const float*)d_in[8];
    const float* bih = (const float*)d_in[9];
    const float* bhh = (const float*)d_in[10];
    float* out = (float*)d_out;

    float *xhi, *xlo, *w1h, *w1l, *w2h, *w2l, *w3h, *w3l;
    float *h1h, *h1l, *h2h, *h2l, *az;
    cudaGetSymbolAddress((void**)&xhi, g_xhi);
    cudaGetSymbolAddress((void**)&xlo, g_xlo);
    cudaGetSymbolAddress((void**)&w1h, g_w1h);
    cudaGetSymbolAddress((void**)&w1l, g_w1l);
    cudaGetSymbolAddress((void**)&w2h, g_w2h);
    cudaGetSymbolAddress((void**)&w2l, g_w2l);
    cudaGetSymbolAddress((void**)&w3h, g_w3h);
    cudaGetSymbolAddress((void**)&w3l, g_w3l);
    cudaGetSymbolAddress((void**)&h1h, g_h1h);
    cudaGetSymbolAddress((void**)&h1l, g_h1l);
    cudaGetSymbolAddress((void**)&h2h, g_h2h);
    cudaGetSymbolAddress((void**)&h2l, g_h2l);
    cudaGetSymbolAddress((void**)&az,  g_az);

    cudaFuncSetAttribute(mma_gemm_split,
                         cudaFuncAttributeMaxDynamicSharedMemorySize, SG_SMEM);
    cudaFuncSetAttribute(lstm_step,
                         cudaFuncAttributeMaxDynamicSharedMemorySize, ST_SMEM);

    // setup
    conv_split<<<5248, 256>>>(zs, W1, W2, W3);
    conv_wc<<<1024, 384>>>(Whh, Wih, bih, bhh);
    init_state<<<4096, 256>>>();

    // MLP (split-tf32)
    mma_gemm_split<<<dim3(4, 32), 256, SG_SMEM>>>(xhi, xlo, w1h, w1l, b1,
                                                  h1h, h1l, BATCH, 512, 256, 1, 512);
    mma_gemm_split<<<dim3(2, 32), 256, SG_SMEM>>>(h1h, h1l, w2h, w2l, b2,
                                                  h2h, h2l, BATCH, 256, 512, 1, 256);
    // z -> tf32 single, strided into g_az cols 256..383
    mma_gemm_split<<<dim3(1, 32), 256, SG_SMEM>>>(h2h, h2l, w3h, w3l, b3,
                                                  az + 256, nullptr, BATCH, 128, 256, 0, KAZ);

    // 50 fused LSTM steps (t=0 uniform: h-part of g_az is zero)
    for (int t = 0; t < T_STEPS; t++)
        lstm_step<<<dim3(4, 32), 512, ST_SMEM>>>(out, t);
}

// round 10
// speedup vs baseline: 1.7317x; 1.7317x over previous
#include <cuda_runtime.h>
#include <cuda_fp16.h>
#include <cstdint>

#define BATCH 4096
#define T_STEPS 50
#define HID 256
#define HSTR (T_STEPS * HID)   // out row stride: 12800 floats

// ---------------- scratch (no allocations allowed) ----------------
__device__ float g_xhi[BATCH * 256],  g_xlo[BATCH * 256];
__device__ float g_w1h[512 * 256],    g_w1l[512 * 256];
__device__ float g_w2h[256 * 512],    g_w2l[256 * 512];
__device__ float g_w3h[128 * 256],    g_w3l[128 * 256];
__device__ float g_wihh[1024 * 128],  g_wihl[1024 * 128];
__device__ float g_h1h[BATCH * 512],  g_h1l[BATCH * 512];
__device__ float g_h2h[BATCH * 256],  g_h2l[BATCH * 256];
__device__ float g_z1h[BATCH * 128],  g_z1l[BATCH * 128];
__device__ float g_xp[1024 * BATCH];          // fp32 TRANSPOSED [1024][4096] (incl. biases)
__device__ float g_c [256  * BATCH];          // fp32 TRANSPOSED [256][4096]
__device__ __half g_ht[BATCH * 256];          // fp16 compact h_{t-1}
__device__ __half g_whhc[1024 * 256];         // fp16 permuted Whh: r' = jb8*128 + g*32 + j

// ---------------- helpers ----------------
__device__ __forceinline__ uint32_t f2tf(float x) {
    uint32_t r;
    asm("cvt.rna.tf32.f32 %0, %1;" : "=r"(r) : "f"(x));
    return r;
}
__device__ __forceinline__ float f2tf_f(float x) { return __uint_as_float(f2tf(x)); }
__device__ __forceinline__ uint32_t smem_u32(const void* p) {
    uint32_t a;
    asm("{ .reg .u64 t; cvta.to.shared.u64 t, %1; cvt.u32.u64 %0, t; }" : "=r"(a) : "l"(p));
    return a;
}
__device__ __forceinline__ void cp16(uint32_t d, const void* s) {
    asm volatile("cp.async.cg.shared.global [%0], [%1], 16;" :: "r"(d), "l"(s));
}
__device__ __forceinline__ void cp_commit() { asm volatile("cp.async.commit_group;"); }
__device__ __forceinline__ void cp_wait1()  { asm volatile("cp.async.wait_group 1;" ::: "memory"); }
__device__ __forceinline__ void cp_wait0()  { asm volatile("cp.async.wait_group 0;" ::: "memory"); }
__device__ __forceinline__ void mma8(float* c, const uint32_t* a, const uint32_t* b) {
    asm volatile(
        "mma.sync.aligned.m16n8k8.row.col.f32.tf32.tf32.f32 "
        "{%0,%1,%2,%3}, {%4,%5,%6,%7}, {%8,%9}, {%0,%1,%2,%3};"
        : "+f"(c[0]), "+f"(c[1]), "+f"(c[2]), "+f"(c[3])
        : "r"(a[0]), "r"(a[1]), "r"(a[2]), "r"(a[3]), "r"(b[0]), "r"(b[1]));
}
__device__ __forceinline__ void mma16(float* c, const uint32_t* a, const uint32_t* b) {
    asm volatile(
        "mma.sync.aligned.m16n8k16.row.col.f32.f16.f16.f32 "
        "{%0,%1,%2,%3}, {%4,%5,%6,%7}, {%8,%9}, {%0,%1,%2,%3};"
        : "+f"(c[0]), "+f"(c[1]), "+f"(c[2]), "+f"(c[3])
        : "r"(a[0]), "r"(a[1]), "r"(a[2]), "r"(a[3]), "r"(b[0]), "r"(b[1]));
}
__device__ __forceinline__ float sigmoidf_fast(float x) {
    return __fdividef(1.0f, 1.0f + __expf(-x));
}
__device__ __forceinline__ float tanhf_fast(float x) {
    return fmaf(2.0f, __fdividef(1.0f, 1.0f + __expf(-2.0f * x)), -1.0f);
}

// ---------------- setup kernels ----------------
__global__ void conv_all(const float* __restrict__ zs, const float* __restrict__ W1,
                         const float* __restrict__ W2, const float* __restrict__ W3,
                         const float* __restrict__ Wih) {
    int i = blockIdx.x * 256 + threadIdx.x;
    const float* s; float *hi, *lo; int off;
    if      (i < 1048576) { s = zs;  hi = g_xhi;  lo = g_xlo;  off = i; }
    else if (i < 1179648) { s = W1;  hi = g_w1h;  lo = g_w1l;  off = i - 1048576; }
    else if (i < 1310720) { s = W2;  hi = g_w2h;  lo = g_w2l;  off = i - 1179648; }
    else if (i < 1343488) { s = W3;  hi = g_w3h;  lo = g_w3l;  off = i - 1310720; }
    else                  { s = Wih; hi = g_wihh; lo = g_wihl; off = i - 1343488; }
    float x = s[off];
    float h = f2tf_f(x);
    hi[off] = h;
    lo[off] = f2tf_f(x - h);
}
// fp16 permuted Whh; also zero g_c
__global__ void conv_whh(const float* __restrict__ whh) {
    int k = threadIdx.x, r = blockIdx.x;                 // r 0..1023
    int jb8 = r >> 7, g = (r >> 5) & 3, j = r & 31;
    int gr = g * 256 + jb8 * 32 + j;
    g_whhc[r * 256 + k] = __float2half(whh[(size_t)gr * 256 + k]);
}
__global__ void init_c() {
    int i = blockIdx.x * 256 + threadIdx.x;
    g_c[i] = 0.0f;
}

// ================= split-tf32 GEMM (MLP), 256 threads, 128x128 tile =========
#define SG_STRIDE 36
#define SG_HALF   (128 * SG_STRIDE * 4)   // 18432
#define SG_STAGE  (4 * SG_HALF)           // 73728
#define SG_SMEM   (3 * SG_STAGE)          // 221184
#define SG_GS     133

__device__ __forceinline__ void sg_issue(char* sm, int st,
    const float* Ahi, const float* Alo, const float* Bhi, const float* Blo,
    int aBase, int bBase, int K, int tid)
{
    uint32_t base = smem_u32(sm + (st % 3) * SG_STAGE);
    const int k0 = st * 32;
    const int srow = tid >> 3, sk4 = (tid & 7) << 2;
    #pragma unroll
    for (int i = 0; i < 4; i++) {
        int row = i * 32 + srow;
        uint32_t d = base + (uint32_t)(row * SG_STRIDE + sk4) * 4;
        size_t ao = (size_t)(aBase + row) * K + k0 + sk4;
        size_t bo = (size_t)(bBase + row) * K + k0 + sk4;
        cp16(d,               Ahi + ao);
        cp16(d + SG_HALF,     Alo + ao);
        cp16(d + 2 * SG_HALF, Bhi + bo);
        cp16(d + 3 * SG_HALF, Blo + bo);
    }
    cp_commit();
}

__global__ void __launch_bounds__(256, 1) mma_gemm_split(
    const float* __restrict__ Ahi, const float* __restrict__ Alo,
    const float* __restrict__ Bhi, const float* __restrict__ Blo,
    const float* __restrict__ bias, const float* __restrict__ bias2,
    float* __restrict__ Chi, float* __restrict__ Clo,  // Clo==null -> fp32 out
    int M, int N, int K, int relu, int transC)
{
    extern __shared__ char sm[];
    const int tid = threadIdx.x;
    const int wid = tid >> 5, lane = tid & 31;
    const int wm = wid & 3, wn = wid >> 2;
    const int bm = blockIdx.y * 128, bn = blockIdx.x * 128;
    const int NC = K >> 5;

    float acc[2][8][4];
    #pragma unroll
    for (int mi = 0; mi < 2; mi++)
        #pragma unroll
        for (int ni = 0; ni < 8; ni++)
            #pragma unroll
            for (int v = 0; v < 4; v++) acc[mi][ni][v] = 0.0f;

    sg_issue(sm, 0, Ahi, Alo, Bhi, Blo, bm, bn, K, tid);
    sg_issue(sm, 1, Ahi, Alo, Bhi, Blo, bm, bn, K, tid);

    const int ar = wm * 32 + (lane >> 2);
    const int bc = wn * 64 + (lane >> 2);
    const int q  = lane & 3;

    #pragma unroll 1
    for (int ch = 0; ch < NC; ch++) {
        if (ch == NC - 1) cp_wait0(); else cp_wait1();
        __syncthreads();
        if (ch + 2 < NC) sg_issue(sm, ch + 2, Ahi, Alo, Bhi, Blo, bm, bn, K, tid);
        const uint32_t* Ah = (const uint32_t*)(sm + (ch % 3) * SG_STAGE);
        const uint32_t* Al = Ah + SG_HALF / 4;
        const uint32_t* Bh = Ah + 2 * SG_HALF / 4;
        const uint32_t* Bl = Ah + 3 * SG_HALF / 4;
        #pragma unroll
        for (int kk = 0; kk < 4; kk++) {
            const int kb = kk * 8 + q;
            uint32_t ah[2][4], al[2][4], bh[8][2], bl[8][2];
            #pragma unroll
            for (int mi = 0; mi < 2; mi++) {
                const int r0 = (ar + mi * 16) * SG_STRIDE;
                const int r8 = (ar + mi * 16 + 8) * SG_STRIDE;
                ah[mi][0] = Ah[r0 + kb]; ah[mi][1] = Ah[r8 + kb];
                ah[mi][2] = Ah[r0 + kb + 4]; ah[mi][3] = Ah[r8 + kb + 4];
                al[mi][0] = Al[r0 + kb]; al[mi][1] = Al[r8 + kb];
                al[mi][2] = Al[r0 + kb + 4]; al[mi][3] = Al[r8 + kb + 4];
            }
            #pragma unroll
            for (int ni = 0; ni < 8; ni++) {
                const int rB = (bc + ni * 8) * SG_STRIDE;
                bh[ni][0] = Bh[rB + kb]; bh[ni][1] = Bh[rB + kb + 4];
                bl[ni][0] = Bl[rB + kb]; bl[ni][1] = Bl[rB + kb + 4];
            }
            #pragma unroll
            for (int mi = 0; mi < 2; mi++)
                #pragma unroll
                for (int ni = 0; ni < 8; ni++) {
                    mma8(acc[mi][ni], ah[mi], bl[ni]);
                    mma8(acc[mi][ni], al[mi], bh[ni]);
                    mma8(acc[mi][ni], ah[mi], bh[ni]);
                }
        }
    }
    __syncthreads();

    {
        float* gs = (float*)sm;
        const int grow = wm * 32 + (lane >> 2);
        const int gcol = wn * 64 + ((lane & 3) << 1);
        #pragma unroll
        for (int mi = 0; mi < 2; mi++)
            #pragma unroll
            for (int ni = 0; ni < 8; ni++) {
                int r = grow + mi * 16, cc = gcol + ni * 8;
                gs[r * SG_GS + cc]           = acc[mi][ni][0];
                gs[r * SG_GS + cc + 1]       = acc[mi][ni][1];
                gs[(r + 8) * SG_GS + cc]     = acc[mi][ni][2];
                gs[(r + 8) * SG_GS + cc + 1] = acc[mi][ni][3];
            }
    }
    __syncthreads();

    const float* gs = (const float*)sm;
    if (!transC) {
        #pragma unroll
        for (int i = 0; i < 16; i++) {
            int row = i * 8 + wid;
            #pragma unroll
            for (int cc = 0; cc < 4; cc++) {
                int col = cc * 32 + lane;
                float bv = bias[bn + col];
                if (bias2) bv += bias2[bn + col];
                float v = gs[row * SG_GS + col] + bv;
                if (relu) v = fmaxf(v, 0.0f);
                size_t o = (size_t)(bm + row) * N + bn + col;
                if (Clo) {
                    float h = f2tf_f(v);
                    Chi[o] = h;
                    Clo[o] = f2tf_f(v - h);
                } else Chi[o] = v;
            }
        }
    } else {
        #pragma unroll
        for (int i = 0; i < 16; i++) {
            int col = i * 8 + wid;
            float bv = bias[bn + col];
            if (bias2) bv += bias2[bn + col];
            #pragma unroll
            for (int cc = 0; cc < 4; cc++) {
                int row = cc * 32 + lane;
                float v = gs[row * SG_GS + col] + bv;
                if (relu) v = fmaxf(v, 0.0f);
                Chi[(size_t)(bn + col) * M + bm + row] = v;
            }
        }
    }
}

// ================= fp16 LSTM step, 512 threads, 256x128 tile, single wave ====
// gates[256 batch rows][128 cols=(g,j)] = h_{t-1}(fp16) @ Whh_perm(fp16)^T, K=256.
// m16n8k16 fragments: q=lane&3, r=lane>>2;
//   a0=(r,2q:2q+1) a1=(r+8,..) a2=(r,2q+8:2q+9) a3=(r+8,..); b0=(c,2q:2q+1) b1=(c,2q+8:..)
// Row stride 72 halves (36 words): word bank = (4r+q) mod 32 -> conflict-free.
#define SH_W    36                         // words per staged row (72 halves)
#define ST_A    (256 * SH_W * 4)           // 36864
#define ST_B    (128 * SH_W * 4)           // 18432
#define ST_STAGE (ST_A + ST_B)             // 55296 ; 3 stages = 165888
#define ST_GS   133
#define ST_HS   (256 * ST_GS * 4)          // 136192
#define ST_SMEM (ST_HS + 256 * 33 * 4)     // 169984 (aliases stage area)

__device__ __forceinline__ void st_issue(char* sm, int st, int bm, int bBase, int tid)
{
    uint32_t base = smem_u32(sm + (st % 3) * ST_STAGE);
    const int k0 = st * 64;                       // halves
    const int srow = tid >> 3;                    // 0..63
    const int skw  = (tid & 7) << 2;              // word offset 0..28 (8 halves each)
    #pragma unroll
    for (int i = 0; i < 4; i++) {
        int row = i * 64 + srow;
        cp16(base + (uint32_t)(row * SH_W + skw) * 4,
             g_ht + (size_t)(bm + row) * HID + k0 + skw * 2);
    }
    #pragma unroll
    for (int i = 0; i < 2; i++) {
        int row = i * 64 + srow;
        cp16(base + ST_A + (uint32_t)(row * SH_W + skw) * 4,
             g_whhc + (size_t)(bBase + row) * HID + k0 + skw * 2);
    }
    cp_commit();
}

__global__ void __launch_bounds__(512, 1)
lstm_step(float* __restrict__ out, int t)
{
    extern __shared__ char sm[];
    const int tid  = threadIdx.x;
    const int wid  = tid >> 5;
    const int lane = tid & 31;
    const int wm   = wid & 7, wn = wid >> 3;   // 8 x 2 warp grid (32x64 tiles)
    const int bm   = blockIdx.y * 256;
    const int jb   = blockIdx.x * 32;
    const int bBase = blockIdx.x * 128;        // g_whhc rows for this jb

    if (t > 0) {
        float acc[2][8][4];
        #pragma unroll
        for (int mi = 0; mi < 2; mi++)
            #pragma unroll
            for (int ni = 0; ni < 8; ni++)
                #pragma unroll
                for (int v = 0; v < 4; v++) acc[mi][ni][v] = 0.0f;

        st_issue(sm, 0, bm, bBase, tid);
        st_issue(sm, 1, bm, bBase, tid);

        const int ar = wm * 32 + (lane >> 2);
        const int bc = wn * 64 + (lane >> 2);
        const int q  = lane & 3;

        #pragma unroll 1
        for (int ch = 0; ch < 4; ch++) {
            if (ch == 3) cp_wait0(); else cp_wait1();
            __syncthreads();
            if (ch + 2 < 4) st_issue(sm, ch + 2, bm, bBase, tid);
            const uint32_t* As = (const uint32_t*)(sm + (ch % 3) * ST_STAGE);
            const uint32_t* Bs = As + ST_A / 4;
            #pragma unroll
            for (int ks = 0; ks < 4; ks++) {
                const int kb = ks * 8 + q;
                uint32_t a[2][4], b[8][2];
                #pragma unroll
                for (int mi = 0; mi < 2; mi++) {
                    const int r0 = (ar + mi * 16) * SH_W;
                    const int r8 = (ar + mi * 16 + 8) * SH_W;
                    a[mi][0] = As[r0 + kb];
                    a[mi][1] = As[r8 + kb];
                    a[mi][2] = As[r0 + kb + 4];
                    a[mi][3] = As[r8 + kb + 4];
                }
                #pragma unroll
                for (int ni = 0; ni < 8; ni++) {
                    const int rB = (bc + ni * 8) * SH_W;
                    b[ni][0] = Bs[rB + kb];
                    b[ni][1] = Bs[rB + kb + 4];
                }
                #pragma unroll
                for (int mi = 0; mi < 2; mi++)
                    #pragma unroll
                    for (int ni = 0; ni < 8; ni++)
                        mma16(acc[mi][ni], a[mi], b[ni]);
            }
        }
        __syncthreads();

        // stage gates: gs[256][133], local col = g*32 + j
        float* gs = (float*)sm;
        const int grow = wm * 32 + (lane >> 2);
        const int gcol = wn * 64 + ((lane & 3) << 1);
        #pragma unroll
        for (int mi = 0; mi < 2; mi++)
            #pragma unroll
            for (int ni = 0; ni < 8; ni++) {
                int r = grow + mi * 16, cc = gcol + ni * 8;
                gs[r * ST_GS + cc]           = acc[mi][ni][0];
                gs[r * ST_GS + cc + 1]       = acc[mi][ni][1];
                gs[(r + 8) * ST_GS + cc]     = acc[mi][ni][2];
                gs[(r + 8) * ST_GS + cc + 1] = acc[mi][ni][3];
            }
        __syncthreads();
    }

    // ---------------- LSTM cell epilogue ----------------
    const float* gs = (const float*)sm;
    float* hsm = (float*)(sm + ST_HS);
    const int rloc = tid & 255;
    const int chalf = tid >> 8;          // 0 or 1
    const int brow = bm + rloc;

    #pragma unroll
    for (int i = 0; i < 16; i++) {
        const int jj = chalf * 16 + i;   // 0..31
        float gi, gf, gg, go;
        if (t > 0) {
            gi = gs[rloc * ST_GS + jj];
            gf = gs[rloc * ST_GS + 32 + jj];
            gg = gs[rloc * ST_GS + 64 + jj];
            go = gs[rloc * ST_GS + 96 + jj];
        } else {
            gi = gf = gg = go = 0.0f;
        }
        gi += g_xp[(size_t)(      jb + jj) * BATCH + brow];
        gf += g_xp[(size_t)(256 + jb + jj) * BATCH + brow];
        gg += g_xp[(size_t)(512 + jb + jj) * BATCH + brow];
        go += g_xp[(size_t)(768 + jb + jj) * BATCH + brow];
        float cp = (t > 0) ? g_c[(size_t)(jb + jj) * BATCH + brow] : 0.0f;
        float vi = sigmoidf_fast(gi);
        float vf = sigmoidf_fast(gf);
        float vg = tanhf_fast(gg);
        float vo = sigmoidf_fast(go);
        float cn = vf * cp + vi * vg;
        g_c[(size_t)(jb + jj) * BATCH + brow] = cn;
        hsm[rloc * 33 + jj] = vo * tanhf_fast(cn);
    }
    __syncthreads();

    // coalesced h writes: out (fp32 strided) + g_ht (fp16 compact)
    #pragma unroll
    for (int i = 0; i < 16; i++) {
        int row = i * 16 + wid;
        float v = hsm[row * 33 + lane];
        out[(size_t)(bm + row) * HSTR + (size_t)t * HID + jb + lane] = v;
        g_ht[(size_t)(bm + row) * HID + jb + lane] = __float2half(v);
    }
}

// ---------------- launch ----------------
extern "C" void kernel_launch(void* const* d_in, const int* in_sizes, int n_in,
                              void* d_out, int out_size)
{
    const float* zs  = (const float*)d_in[0];
    const float* W1  = (const float*)d_in[1];
    const float* b1  = (const float*)d_in[2];
    const float* W2  = (const float*)d_in[3];
    const float* b2  = (const float*)d_in[4];
    const float* W3  = (const float*)d_in[5];
    const float* b3  = (const float*)d_in[6];
    const float* Wih = (const float*)d_in[7];
    const float* Whh = (const float*)d_in[8];
    const float* bih = (const float*)d_in[9];
    const float* bhh = (const float*)d_in[10];
    float* out = (float*)d_out;

    float *xhi, *xlo, *w1h, *w1l, *w2h, *w2l, *w3h, *w3l, *wihh, *wihl;
    float *h1h, *h1l, *h2h, *h2l, *z1h, *z1l, *xp;
    cudaGetSymbolAddress((void**)&xhi,  g_xhi);
    cudaGetSymbolAddress((void**)&xlo,  g_xlo);
    cudaGetSymbolAddress((void**)&w1h,  g_w1h);
    cudaGetSymbolAddress((void**)&w1l,  g_w1l);
    cudaGetSymbolAddress((void**)&w2h,  g_w2h);
    cudaGetSymbolAddress((void**)&w2l,  g_w2l);
    cudaGetSymbolAddress((void**)&w3h,  g_w3h);
    cudaGetSymbolAddress((void**)&w3l,  g_w3l);
    cudaGetSymbolAddress((void**)&wihh, g_wihh);
    cudaGetSymbolAddress((void**)&wihl, g_wihl);
    cudaGetSymbolAddress((void**)&h1h,  g_h1h);
    cudaGetSymbolAddress((void**)&h1l,  g_h1l);
    cudaGetSymbolAddress((void**)&h2h,  g_h2h);
    cudaGetSymbolAddress((void**)&h2l,  g_h2l);
    cudaGetSymbolAddress((void**)&z1h,  g_z1h);
    cudaGetSymbolAddress((void**)&z1l,  g_z1l);
    cudaGetSymbolAddress((void**)&xp,   g_xp);

    cudaFuncSetAttribute(mma_gemm_split,
                         cudaFuncAttributeMaxDynamicSharedMemorySize, SG_SMEM);
    cudaFuncSetAttribute(lstm_step,
                         cudaFuncAttributeMaxDynamicSharedMemorySize, ST_SMEM);

    // setup
    conv_all<<<5760, 256>>>(zs, W1, W2, W3, Wih);
    conv_whh<<<1024, 256>>>(Whh);
    init_c<<<4096, 256>>>();

    // MLP (split-tf32, fp32-grade accuracy)
    mma_gemm_split<<<dim3(4, 32), 256, SG_SMEM>>>(xhi, xlo, w1h, w1l, b1, nullptr,
                                                  h1h, h1l, BATCH, 512, 256, 1, 0);
    mma_gemm_split<<<dim3(2, 32), 256, SG_SMEM>>>(h1h, h1l, w2h, w2l, b2, nullptr,
                                                  h2h, h2l, BATCH, 256, 512, 1, 0);
    mma_gemm_split<<<dim3(1, 32), 256, SG_SMEM>>>(h2h, h2l, w3h, w3l, b3, nullptr,
                                                  z1h, z1l, BATCH, 128, 256, 0, 0);
    // x_part fp32 transposed (includes b_ih + b_hh)
    mma_gemm_split<<<dim3(8, 32), 256, SG_SMEM>>>(z1h, z1l, wihh, wihl, bih, bhh,
                                                  xp, nullptr, BATCH, 1024, 128, 0, 1);

    // 50 fp16 tensor-core LSTM steps (single wave: 8 x 16 = 128 CTAs)
    for (int t = 0; t < T_STEPS; t++)
        lstm_step<<<dim3(8, 16), 512, ST_SMEM>>>(out, t);
}